// round 14
// baseline (speedup 1.0000x reference)
#include <cuda_runtime.h>

#define BB 4
#define KK 200
#define DIMN 256
#define TFRAMES 800
#define TTILE 4

// ---- scratch (no allocations allowed) ----
__device__ float g_start[BB * KK];
__device__ float g_end[BB * KK];
__device__ float g_base1[BB * KK * 16];
__device__ float g_base2[BB * KK * 2];

// silu(x) = 0.5*x*(1 + tanh(x/2)) : 1 MUFU + 2 FMA
__device__ __forceinline__ float silu_f(float x) {
    float hx = 0.5f * x;
    float t;
    asm("tanh.approx.f32 %0, %1;" : "=f"(t) : "f"(hx));
    return fmaf(hx, t, hx);
}

// ---- packed f32x2 helpers (sm_100+; FFMA2 is PTX-only) ----
typedef unsigned long long u64t;
__device__ __forceinline__ u64t pack2(float lo, float hi) {
    u64t r;
    asm("mov.b64 %0, {%1, %2};" : "=l"(r) : "f"(lo), "f"(hi));
    return r;
}
__device__ __forceinline__ void unpack2(u64t v, float& lo, float& hi) {
    asm("mov.b64 {%0, %1}, %2;" : "=f"(lo), "=f"(hi) : "l"(v));
}
__device__ __forceinline__ u64t fma2(u64t a, u64t b, u64t c) {
    u64t d;
    asm("fma.rn.f32x2 %0, %1, %2, %3;" : "=l"(d) : "l"(a), "l"(b), "l"(c));
    return d;
}

// ---------------------------------------------------------------------------
// Kernel A: conv1d+SiLU fold into base vectors; block 100 = durations cumsum.
// ---------------------------------------------------------------------------
__global__ __launch_bounds__(256) void prep_kernel(
    const float* __restrict__ dur, const float* __restrict__ features,
    const float* __restrict__ c1w, const float* __restrict__ c1b,
    const float* __restrict__ c2w, const float* __restrict__ c2b,
    const float* __restrict__ sw1w1, const float* __restrict__ sw1b1,
    const float* __restrict__ sw2w1, const float* __restrict__ sw2b1) {
    int tid = threadIdx.x;
    int lane = tid & 31, w = tid >> 5;

    if (blockIdx.x == 100) {
        if (w < BB) {
            float carry = 0.f;
            for (int c = 0; c < 7; c++) {
                int idx = c * 32 + lane;
                float d = (idx < KK) ? dur[w * KK + idx] : 0.f;
                float v = d;
#pragma unroll
                for (int o = 1; o < 32; o <<= 1) {
                    float u = __shfl_up_sync(0xffffffffu, v, o);
                    if (lane >= o) v += u;
                }
                if (idx < KK) {
                    g_end[w * KK + idx] = carry + v;
                    g_start[w * KK + idx] = carry + v - d;
                }
                carry += __shfl_sync(0xffffffffu, v, 31);
            }
        }
        return;
    }

    int b = blockIdx.x / 25;
    int k0 = (blockIdx.x % 25) * 8;
    __shared__ float featS[10][256];
    __shared__ float convS[8][16];

    for (int i = tid; i < 2560; i += 256) {
        int r = i >> 8, d = i & 255;
        int row = k0 - 1 + r;
        featS[r][d] = (row >= 0 && row < KK) ? features[(b * KK + row) * DIMN + d] : 0.f;
    }
    __syncthreads();

    float acc[16];
#pragma unroll
    for (int c = 0; c < 16; c++) acc[c] = 0.f;
    for (int it = 0; it < 24; it++) {
        int i = it * 32 + lane;
        int j = i >> 8, d = i & 255;
        float f = featS[w + j][d];
        int off = (j * 256 + d) * 8;
        float4 a0 = *reinterpret_cast<const float4*>(c1w + off);
        float4 a1 = *reinterpret_cast<const float4*>(c1w + off + 4);
        float4 b0 = *reinterpret_cast<const float4*>(c2w + off);
        float4 b1 = *reinterpret_cast<const float4*>(c2w + off + 4);
        acc[0] = fmaf(f, a0.x, acc[0]);  acc[1] = fmaf(f, a0.y, acc[1]);
        acc[2] = fmaf(f, a0.z, acc[2]);  acc[3] = fmaf(f, a0.w, acc[3]);
        acc[4] = fmaf(f, a1.x, acc[4]);  acc[5] = fmaf(f, a1.y, acc[5]);
        acc[6] = fmaf(f, a1.z, acc[6]);  acc[7] = fmaf(f, a1.w, acc[7]);
        acc[8]  = fmaf(f, b0.x, acc[8]);  acc[9]  = fmaf(f, b0.y, acc[9]);
        acc[10] = fmaf(f, b0.z, acc[10]); acc[11] = fmaf(f, b0.w, acc[11]);
        acc[12] = fmaf(f, b1.x, acc[12]); acc[13] = fmaf(f, b1.y, acc[13]);
        acc[14] = fmaf(f, b1.z, acc[14]); acc[15] = fmaf(f, b1.w, acc[15]);
    }
#pragma unroll
    for (int c = 0; c < 16; c++) {
        float v = acc[c];
#pragma unroll
        for (int o = 16; o; o >>= 1) v += __shfl_down_sync(0xffffffffu, v, o);
        if (lane == 0) convS[w][c] = v;
    }
    __syncthreads();

    if (tid < 128) {
        int tk = tid >> 4, c = tid & 15;
        float bsl = (c < 8) ? c1b[c] : c2b[c - 8];
        convS[tk][c] = silu_f(convS[tk][c] + bsl);
    }
    __syncthreads();

    if (tid < 128) {
        int tk = tid >> 4, i = tid & 15;
        float s = sw1b1[i];
#pragma unroll
        for (int c = 0; c < 8; c++) s = fmaf(convS[tk][c], sw1w1[(2 + c) * 16 + i], s);
        g_base1[(b * KK + k0 + tk) * 16 + i] = s;
    } else if (tid < 144) {
        int t2 = tid - 128, tk = t2 >> 1, j = t2 & 1;
        float s = sw2b1[j];
#pragma unroll
        for (int c = 0; c < 8; c++) s = fmaf(convS[tk][8 + c], sw2w1[(2 + c) * 2 + j], s);
        g_base2[(b * KK + k0 + tk) * 2 + j] = s;
    }
}

// ---------------------------------------------------------------------------
// Kernel B: fused main. One block = (b, 4 frames); grid 800 -> ~4 resident
// blocks/SM with queue refill (occupancy was grid-limited at TTILE=8).
//   logits (4 frames) -> warps 0-3 softmax -> C phase: 2 chunks x 2 frames
//   (FFMA2 on j, shuffle A-reduce) -> O phase: thread = 1 dim x ALL 4 frames
//   (1 coalesced LDG.32 + 1 uniform LDS.128 per k, F read once per block).
// ---------------------------------------------------------------------------
__global__ __launch_bounds__(256, 4) void main_kernel(
    const float* __restrict__ features,
    const float* __restrict__ sw1w1, const float* __restrict__ sw1w2,
    const float* __restrict__ sw1b2,
    const float* __restrict__ sw2w1, const float* __restrict__ sw2w2,
    const float* __restrict__ sw2b2,
    const float* __restrict__ p1w, const float* __restrict__ p1b,
    const float* __restrict__ p2w, const float* __restrict__ p2b,
    float* __restrict__ out) {
    __shared__ __align__(16) float sE[TTILE][KK];    // raw logits
    __shared__ __align__(16) float sWt[KK][4];       // transposed normalized W
    __shared__ __align__(16) float Csm[2][KK][20];   // W-scaled C, pad 20
    __shared__ __align__(16) float sW2s[256];        // sw1_w2 [16,16]
    __shared__ __align__(16) float sW1p[32];         // interleaved (w1r0, w1r1)
    __shared__ __align__(16) float sB2[16];
    __shared__ float sA[TTILE][16];

    int tid = threadIdx.x;
    int b = blockIdx.y;
    int t0 = blockIdx.x * TTILE;
    int lane = tid & 31, wid = tid >> 5;

    sW2s[tid] = sw1w2[tid];
    if (tid < 16) {
        sW1p[tid * 2]     = sw1w1[tid];
        sW1p[tid * 2 + 1] = sw1w1[16 + tid];
        sB2[tid] = sw1b2[tid];
    }

    float s2r00 = sw2w1[0], s2r01 = sw2w1[1];
    float s2r10 = sw2w1[2], s2r11 = sw2w1[3];
    float w20 = sw2w2[0], w21 = sw2w2[1], w22 = sw2w2[2], w23 = sw2w2[3];
    float b20 = sw2b2[0], b21 = sw2b2[1];
    float p10 = p1w[0], p11 = p1w[1], pb1 = p1b[0];

    float base1[16];
    float base2_0 = 0.f, base2_1 = 0.f, startk = 0.f, endk = 0.f;
    if (tid < KK) {
        startk = g_start[b * KK + tid];
        endk   = g_end[b * KK + tid];
        const float4* bp = reinterpret_cast<const float4*>(g_base1 + (b * KK + tid) * 16);
#pragma unroll
        for (int q = 0; q < 4; q++) {
            float4 v = bp[q];
            base1[q * 4 + 0] = v.x; base1[q * 4 + 1] = v.y;
            base1[q * 4 + 2] = v.z; base1[q * 4 + 3] = v.w;
        }
        base2_0 = g_base2[(b * KK + tid) * 2 + 0];
        base2_1 = g_base2[(b * KK + tid) * 2 + 1];
    }

    // ---- logits for 4 frames ----
    if (tid < KK) {
#pragma unroll
        for (int tt = 0; tt < TTILE; tt++) {
            float t = (float)(t0 + tt);
            float S = t - startk, E = endk - t;
            float g0  = silu_f(fmaf(S, s2r00, fmaf(E, s2r10, base2_0)));
            float g1  = silu_f(fmaf(S, s2r01, fmaf(E, s2r11, base2_1)));
            float rr0 = silu_f(fmaf(g0, w20, fmaf(g1, w22, b20)));
            float rr1 = silu_f(fmaf(g0, w21, fmaf(g1, w23, b21)));
            sE[tt][tid] = fmaf(rr0, p10, fmaf(rr1, p11, pb1));
        }
    }
    __syncthreads();

    // ---- warps 0-3: softmax of frame wid -> transposed sWt[k][wid] ----
    if (wid < TTILE) {
        float v[7];
        float m = -1e30f;
#pragma unroll
        for (int c = 0; c < 7; c++) {
            int idx = c * 32 + lane;
            v[c] = (idx < KK) ? sE[wid][idx] : -1e30f;
            m = fmaxf(m, v[c]);
        }
#pragma unroll
        for (int o = 16; o; o >>= 1) m = fmaxf(m, __shfl_xor_sync(0xffffffffu, m, o));
        float s = 0.f;
#pragma unroll
        for (int c = 0; c < 7; c++) {
            v[c] = __expf(v[c] - m);
            if (c * 32 + lane < KK) s += v[c];
        }
#pragma unroll
        for (int o = 16; o; o >>= 1) s += __shfl_xor_sync(0xffffffffu, s, o);
        float invs = 1.0f / s;
#pragma unroll
        for (int c = 0; c < 7; c++) {
            int idx = c * 32 + lane;
            if (idx < KK) sWt[idx][wid] = v[c] * invs;
        }
    }
    __syncthreads();

    // ---- C phase + shuffle-reduced A, 2 chunks x 2 register-blocked frames ----
    const float2* w1v = reinterpret_cast<const float2*>(sW1p);
    for (int half = 0; half < 2; half++) {
        if (tid < KK) {
            float tA = (float)(t0 + half * 2);
            float S0 = tA - startk, E0 = endk - tA;
            float S1 = S0 + 1.0f,   E1 = E0 - 1.0f;
            u64t accC2[2][8];
            {
                const u64t* b2v = reinterpret_cast<const u64t*>(sB2);
#pragma unroll
                for (int j2 = 0; j2 < 8; j2++) {
                    u64t bv = b2v[j2];
                    accC2[0][j2] = bv;
                    accC2[1][j2] = bv;
                }
            }
#pragma unroll
            for (int i = 0; i < 16; i++) {
                float2 wp = w1v[i];
                float h0 = silu_f(fmaf(S0, wp.x, fmaf(E0, wp.y, base1[i])));
                float h1 = silu_f(fmaf(S1, wp.x, fmaf(E1, wp.y, base1[i])));
                u64t h02 = pack2(h0, h0);
                u64t h12 = pack2(h1, h1);
                const ulonglong2* wrow = reinterpret_cast<const ulonglong2*>(sW2s + i * 16);
#pragma unroll
                for (int jq = 0; jq < 4; jq++) {
                    ulonglong2 wv = wrow[jq];
                    accC2[0][jq * 2 + 0] = fma2(h02, wv.x, accC2[0][jq * 2 + 0]);
                    accC2[0][jq * 2 + 1] = fma2(h02, wv.y, accC2[0][jq * 2 + 1]);
                    accC2[1][jq * 2 + 0] = fma2(h12, wv.x, accC2[1][jq * 2 + 0]);
                    accC2[1][jq * 2 + 1] = fma2(h12, wv.y, accC2[1][jq * 2 + 1]);
                }
            }
            float wk0 = sWt[tid][half * 2 + 0];
            float wk1 = sWt[tid][half * 2 + 1];
#pragma unroll
            for (int jq = 0; jq < 4; jq++) {
                float a0, a1, a2, a3;
                float4 c0, c1;
                unpack2(accC2[0][jq * 2 + 0], a0, a1);
                unpack2(accC2[0][jq * 2 + 1], a2, a3);
                c0.x = wk0 * silu_f(a0); c0.y = wk0 * silu_f(a1);
                c0.z = wk0 * silu_f(a2); c0.w = wk0 * silu_f(a3);
                unpack2(accC2[1][jq * 2 + 0], a0, a1);
                unpack2(accC2[1][jq * 2 + 1], a2, a3);
                c1.x = wk1 * silu_f(a0); c1.y = wk1 * silu_f(a1);
                c1.z = wk1 * silu_f(a2); c1.w = wk1 * silu_f(a3);
                *reinterpret_cast<float4*>(&Csm[0][tid][jq * 4]) = c0;
                *reinterpret_cast<float4*>(&Csm[1][tid][jq * 4]) = c1;
            }
        }
        __syncthreads();
        {   // A-reduce: (u, p, ch-of-25) strips, shuffle over ch bits. CF banks.
            int u = tid >> 7, p = (tid >> 3) & 15, ch = tid & 7;
            float s = 0.f;
            int kbeg = ch * 25;
#pragma unroll 5
            for (int k = kbeg; k < kbeg + 25; k++) s += Csm[u][k][p];
            s += __shfl_xor_sync(0xffffffffu, s, 4);
            s += __shfl_xor_sync(0xffffffffu, s, 2);
            s += __shfl_xor_sync(0xffffffffu, s, 1);
            if (ch == 0) sA[half * 2 + u][p] = s;
        }
        __syncthreads();
    }

    // ---- O phase: thread = 1 dim x all 4 frames; F read once per block ----
    int d = tid;
    u64t a01 = 0ull, a23 = 0ull;   // lanes = (frame0,frame1), (frame2,frame3)
    const float* F = features + b * KK * DIMN + d;
    for (int k = 0; k < KK; k += 2) {
        float f0 = F[k * DIMN];
        float f1 = F[(k + 1) * DIMN];
        ulonglong2 w0 = *reinterpret_cast<const ulonglong2*>(&sWt[k][0]);
        ulonglong2 w1 = *reinterpret_cast<const ulonglong2*>(&sWt[k + 1][0]);
        u64t ff0 = pack2(f0, f0);
        u64t ff1 = pack2(f1, f1);
        a01 = fma2(ff0, w0.x, a01);
        a23 = fma2(ff0, w0.y, a23);
        a01 = fma2(ff1, w1.x, a01);
        a23 = fma2(ff1, w1.y, a23);
    }

    // ---- epilogue: 4 frames x 1 dim ----
    {
        float o0, o1, o2, o3;
        unpack2(a01, o0, o1);
        unpack2(a23, o2, o3);
        float pb = p2b[d];
        float r0 = o0 + pb, r1 = o1 + pb, r2 = o2 + pb, r3 = o3 + pb;
#pragma unroll
        for (int p = 0; p < 16; p++) {
            float pwv = p2w[p * DIMN + d];
            r0 = fmaf(sA[0][p], pwv, r0);
            r1 = fmaf(sA[1][p], pwv, r1);
            r2 = fmaf(sA[2][p], pwv, r2);
            r3 = fmaf(sA[3][p], pwv, r3);
        }
        int row = (b * TFRAMES + t0) * DIMN + d;
        out[row] = r0;
        out[row + DIMN] = r1;
        out[row + 2 * DIMN] = r2;
        out[row + 3 * DIMN] = r3;
    }
}

// ---------------------------------------------------------------------------
extern "C" void kernel_launch(void* const* d_in, const int* in_sizes, int n_in,
                              void* d_out, int out_size) {
    const float* dur      = (const float*)d_in[1];
    const float* features = (const float*)d_in[2];
    const float* c1w      = (const float*)d_in[3];
    const float* c1b      = (const float*)d_in[4];
    const float* c2w      = (const float*)d_in[5];
    const float* c2b      = (const float*)d_in[6];
    const float* sw1w1    = (const float*)d_in[7];
    const float* sw1b1    = (const float*)d_in[8];
    const float* sw1w2    = (const float*)d_in[9];
    const float* sw1b2    = (const float*)d_in[10];
    const float* sw2w1    = (const float*)d_in[11];
    const float* sw2b1    = (const float*)d_in[12];
    const float* sw2w2    = (const float*)d_in[13];
    const float* sw2b2    = (const float*)d_in[14];
    const float* p1w      = (const float*)d_in[15];
    const float* p1b      = (const float*)d_in[16];
    const float* p2w      = (const float*)d_in[17];
    const float* p2b      = (const float*)d_in[18];
    float* out = (float*)d_out;

    prep_kernel<<<101, 256>>>(dur, features, c1w, c1b, c2w, c2b,
                              sw1w1, sw1b1, sw2w1, sw2b1);
    main_kernel<<<dim3(TFRAMES / TTILE, BB), 256>>>(
        features, sw1w1, sw1w2, sw1b2, sw2w1, sw2w2, sw2b2,
        p1w, p1b, p2w, p2b, out);
}

// round 15
// speedup vs baseline: 1.0838x; 1.0838x over previous
#include <cuda_runtime.h>

#define BB 4
#define KK 200
#define DIMN 256
#define TFRAMES 800
#define TTILE 8

// ---- scratch (no allocations allowed) ----
__device__ float g_start[BB * KK];
__device__ float g_end[BB * KK];
__device__ float g_base1[BB * KK * 16];
__device__ float g_base2[BB * KK * 2];

// silu(x) = 0.5*x*(1 + tanh(x/2)) : 1 MUFU + 2 FMA
__device__ __forceinline__ float silu_f(float x) {
    float hx = 0.5f * x;
    float t;
    asm("tanh.approx.f32 %0, %1;" : "=f"(t) : "f"(hx));
    return fmaf(hx, t, hx);
}

// ---- packed f32x2 helpers (sm_100+; FFMA2 is PTX-only) ----
typedef unsigned long long u64t;
__device__ __forceinline__ u64t pack2(float lo, float hi) {
    u64t r;
    asm("mov.b64 %0, {%1, %2};" : "=l"(r) : "f"(lo), "f"(hi));
    return r;
}
__device__ __forceinline__ void unpack2(u64t v, float& lo, float& hi) {
    asm("mov.b64 {%0, %1}, %2;" : "=f"(lo), "=f"(hi) : "l"(v));
}
__device__ __forceinline__ u64t fma2(u64t a, u64t b, u64t c) {
    u64t d;
    asm("fma.rn.f32x2 %0, %1, %2, %3;" : "=l"(d) : "l"(a), "l"(b), "l"(c));
    return d;
}

// ---------------------------------------------------------------------------
// Kernel A: conv1d+SiLU fold into base vectors; block 100 = durations cumsum.
// Triggers the PDL secondary as each block finishes its writes.
// ---------------------------------------------------------------------------
__global__ __launch_bounds__(256) void prep_kernel(
    const float* __restrict__ dur, const float* __restrict__ features,
    const float* __restrict__ c1w, const float* __restrict__ c1b,
    const float* __restrict__ c2w, const float* __restrict__ c2b,
    const float* __restrict__ sw1w1, const float* __restrict__ sw1b1,
    const float* __restrict__ sw2w1, const float* __restrict__ sw2b1) {
    int tid = threadIdx.x;
    int lane = tid & 31, w = tid >> 5;

    if (blockIdx.x == 100) {
        if (w < BB) {
            float carry = 0.f;
            for (int c = 0; c < 7; c++) {
                int idx = c * 32 + lane;
                float d = (idx < KK) ? dur[w * KK + idx] : 0.f;
                float v = d;
#pragma unroll
                for (int o = 1; o < 32; o <<= 1) {
                    float u = __shfl_up_sync(0xffffffffu, v, o);
                    if (lane >= o) v += u;
                }
                if (idx < KK) {
                    g_end[w * KK + idx] = carry + v;
                    g_start[w * KK + idx] = carry + v - d;
                }
                carry += __shfl_sync(0xffffffffu, v, 31);
            }
        }
#if __CUDA_ARCH__ >= 900
        cudaTriggerProgrammaticLaunchCompletion();
#endif
        return;
    }

    int b = blockIdx.x / 25;
    int k0 = (blockIdx.x % 25) * 8;
    __shared__ float featS[10][256];
    __shared__ float convS[8][16];

    for (int i = tid; i < 2560; i += 256) {
        int r = i >> 8, d = i & 255;
        int row = k0 - 1 + r;
        featS[r][d] = (row >= 0 && row < KK) ? features[(b * KK + row) * DIMN + d] : 0.f;
    }
    __syncthreads();

    float acc[16];
#pragma unroll
    for (int c = 0; c < 16; c++) acc[c] = 0.f;
    for (int it = 0; it < 24; it++) {
        int i = it * 32 + lane;
        int j = i >> 8, d = i & 255;
        float f = featS[w + j][d];
        int off = (j * 256 + d) * 8;
        float4 a0 = *reinterpret_cast<const float4*>(c1w + off);
        float4 a1 = *reinterpret_cast<const float4*>(c1w + off + 4);
        float4 b0 = *reinterpret_cast<const float4*>(c2w + off);
        float4 b1 = *reinterpret_cast<const float4*>(c2w + off + 4);
        acc[0] = fmaf(f, a0.x, acc[0]);  acc[1] = fmaf(f, a0.y, acc[1]);
        acc[2] = fmaf(f, a0.z, acc[2]);  acc[3] = fmaf(f, a0.w, acc[3]);
        acc[4] = fmaf(f, a1.x, acc[4]);  acc[5] = fmaf(f, a1.y, acc[5]);
        acc[6] = fmaf(f, a1.z, acc[6]);  acc[7] = fmaf(f, a1.w, acc[7]);
        acc[8]  = fmaf(f, b0.x, acc[8]);  acc[9]  = fmaf(f, b0.y, acc[9]);
        acc[10] = fmaf(f, b0.z, acc[10]); acc[11] = fmaf(f, b0.w, acc[11]);
        acc[12] = fmaf(f, b1.x, acc[12]); acc[13] = fmaf(f, b1.y, acc[13]);
        acc[14] = fmaf(f, b1.z, acc[14]); acc[15] = fmaf(f, b1.w, acc[15]);
    }
#pragma unroll
    for (int c = 0; c < 16; c++) {
        float v = acc[c];
#pragma unroll
        for (int o = 16; o; o >>= 1) v += __shfl_down_sync(0xffffffffu, v, o);
        if (lane == 0) convS[w][c] = v;
    }
    __syncthreads();

    if (tid < 128) {
        int tk = tid >> 4, c = tid & 15;
        float bsl = (c < 8) ? c1b[c] : c2b[c - 8];
        convS[tk][c] = silu_f(convS[tk][c] + bsl);
    }
    __syncthreads();

    if (tid < 128) {
        int tk = tid >> 4, i = tid & 15;
        float s = sw1b1[i];
#pragma unroll
        for (int c = 0; c < 8; c++) s = fmaf(convS[tk][c], sw1w1[(2 + c) * 16 + i], s);
        g_base1[(b * KK + k0 + tk) * 16 + i] = s;
    } else if (tid < 144) {
        int t2 = tid - 128, tk = t2 >> 1, j = t2 & 1;
        float s = sw2b1[j];
#pragma unroll
        for (int c = 0; c < 8; c++) s = fmaf(convS[tk][8 + c], sw2w1[(2 + c) * 2 + j], s);
        g_base2[(b * KK + k0 + tk) * 2 + j] = s;
    }
#if __CUDA_ARCH__ >= 900
    cudaTriggerProgrammaticLaunchCompletion();
#endif
}

// ---------------------------------------------------------------------------
// Kernel B (PDL secondary): fused main, R12 configuration (proven 34.5us).
// Prep-independent preamble runs BEFORE cudaGridDependencySynchronize();
// g_* reads after. One block = (b, 8 frames).
// ---------------------------------------------------------------------------
__global__ __launch_bounds__(256, 3) void main_kernel(
    const float* __restrict__ features,
    const float* __restrict__ sw1w1, const float* __restrict__ sw1w2,
    const float* __restrict__ sw1b2,
    const float* __restrict__ sw2w1, const float* __restrict__ sw2w2,
    const float* __restrict__ sw2b2,
    const float* __restrict__ p1w, const float* __restrict__ p1b,
    const float* __restrict__ p2w, const float* __restrict__ p2b,
    float* __restrict__ out) {
    __shared__ __align__(16) float sE[TTILE][KK];    // raw logits
    __shared__ __align__(16) float sWt[KK][8];       // transposed normalized W
    __shared__ __align__(16) float Csm[2][KK][20];   // W-scaled C, pad 20
    __shared__ __align__(16) float sW2s[256];        // sw1_w2 [16,16]
    __shared__ __align__(16) float sW1p[32];         // interleaved (w1r0, w1r1)
    __shared__ __align__(16) float sB2[16];
    __shared__ float sPart[2][16][8];
    __shared__ float sA[TTILE][16];

    int tid = threadIdx.x;
    int b = blockIdx.y;
    int t0 = blockIdx.x * TTILE;
    int lane = tid & 31, wid = tid >> 5;

    // ---- prep-independent preamble (harness inputs only) ----
    sW2s[tid] = sw1w2[tid];
    if (tid < 16) {
        sW1p[tid * 2]     = sw1w1[tid];
        sW1p[tid * 2 + 1] = sw1w1[16 + tid];
        sB2[tid] = sw1b2[tid];
    }
    float s2r00 = sw2w1[0], s2r01 = sw2w1[1];
    float s2r10 = sw2w1[2], s2r11 = sw2w1[3];
    float w20 = sw2w2[0], w21 = sw2w2[1], w22 = sw2w2[2], w23 = sw2w2[3];
    float b20 = sw2b2[0], b21 = sw2b2[1];
    float p10 = p1w[0], p11 = p1w[1], pb1 = p1b[0];

#if __CUDA_ARCH__ >= 900
    cudaGridDependencySynchronize();   // wait for prep's g_* writes
#endif

    float base1[16];
    float base2_0 = 0.f, base2_1 = 0.f, startk = 0.f, endk = 0.f;
    if (tid < KK) {
        startk = g_start[b * KK + tid];
        endk   = g_end[b * KK + tid];
        const float4* bp = reinterpret_cast<const float4*>(g_base1 + (b * KK + tid) * 16);
#pragma unroll
        for (int q = 0; q < 4; q++) {
            float4 v = bp[q];
            base1[q * 4 + 0] = v.x; base1[q * 4 + 1] = v.y;
            base1[q * 4 + 2] = v.z; base1[q * 4 + 3] = v.w;
        }
        base2_0 = g_base2[(b * KK + tid) * 2 + 0];
        base2_1 = g_base2[(b * KK + tid) * 2 + 1];
    }

    // ---- logits for all 8 frames ----
    if (tid < KK) {
#pragma unroll
        for (int tt = 0; tt < TTILE; tt++) {
            float t = (float)(t0 + tt);
            float S = t - startk, E = endk - t;
            float g0  = silu_f(fmaf(S, s2r00, fmaf(E, s2r10, base2_0)));
            float g1  = silu_f(fmaf(S, s2r01, fmaf(E, s2r11, base2_1)));
            float rr0 = silu_f(fmaf(g0, w20, fmaf(g1, w22, b20)));
            float rr1 = silu_f(fmaf(g0, w21, fmaf(g1, w23, b21)));
            sE[tt][tid] = fmaf(rr0, p10, fmaf(rr1, p11, pb1));
        }
    }
    __syncthreads();

    // ---- warp wid: softmax of frame wid -> transposed sWt[k][wid] ----
    {
        float v[7];
        float m = -1e30f;
#pragma unroll
        for (int c = 0; c < 7; c++) {
            int idx = c * 32 + lane;
            v[c] = (idx < KK) ? sE[wid][idx] : -1e30f;
            m = fmaxf(m, v[c]);
        }
#pragma unroll
        for (int o = 16; o; o >>= 1) m = fmaxf(m, __shfl_xor_sync(0xffffffffu, m, o));
        float s = 0.f;
#pragma unroll
        for (int c = 0; c < 7; c++) {
            v[c] = __expf(v[c] - m);
            if (c * 32 + lane < KK) s += v[c];
        }
#pragma unroll
        for (int o = 16; o; o >>= 1) s += __shfl_xor_sync(0xffffffffu, s, o);
        float invs = 1.0f / s;
#pragma unroll
        for (int c = 0; c < 7; c++) {
            int idx = c * 32 + lane;
            if (idx < KK) sWt[idx][wid] = v[c] * invs;
        }
    }
    __syncthreads();

    // ---- C phase + A reduction, 2 register-blocked frames, FFMA2 on j ----
    const float2* w1v = reinterpret_cast<const float2*>(sW1p);
    for (int half = 0; half < 4; half++) {
        if (tid < KK) {
            float tA = (float)(t0 + half * 2);
            float S0 = tA - startk, E0 = endk - tA;
            float S1 = S0 + 1.0f,   E1 = E0 - 1.0f;
            u64t accC2[2][8];
            {
                const u64t* b2v = reinterpret_cast<const u64t*>(sB2);
#pragma unroll
                for (int j2 = 0; j2 < 8; j2++) {
                    u64t bv = b2v[j2];
                    accC2[0][j2] = bv;
                    accC2[1][j2] = bv;
                }
            }
#pragma unroll
            for (int i = 0; i < 16; i++) {
                float2 wp = w1v[i];
                float h0 = silu_f(fmaf(S0, wp.x, fmaf(E0, wp.y, base1[i])));
                float h1 = silu_f(fmaf(S1, wp.x, fmaf(E1, wp.y, base1[i])));
                u64t h02 = pack2(h0, h0);
                u64t h12 = pack2(h1, h1);
                const ulonglong2* wrow = reinterpret_cast<const ulonglong2*>(sW2s + i * 16);
#pragma unroll
                for (int jq = 0; jq < 4; jq++) {
                    ulonglong2 wv = wrow[jq];
                    accC2[0][jq * 2 + 0] = fma2(h02, wv.x, accC2[0][jq * 2 + 0]);
                    accC2[0][jq * 2 + 1] = fma2(h02, wv.y, accC2[0][jq * 2 + 1]);
                    accC2[1][jq * 2 + 0] = fma2(h12, wv.x, accC2[1][jq * 2 + 0]);
                    accC2[1][jq * 2 + 1] = fma2(h12, wv.y, accC2[1][jq * 2 + 1]);
                }
            }
            float wk0 = sWt[tid][half * 2 + 0];
            float wk1 = sWt[tid][half * 2 + 1];
#pragma unroll
            for (int jq = 0; jq < 4; jq++) {
                float a0, a1, a2, a3;
                float4 c0, c1;
                unpack2(accC2[0][jq * 2 + 0], a0, a1);
                unpack2(accC2[0][jq * 2 + 1], a2, a3);
                c0.x = wk0 * silu_f(a0); c0.y = wk0 * silu_f(a1);
                c0.z = wk0 * silu_f(a2); c0.w = wk0 * silu_f(a3);
                unpack2(accC2[1][jq * 2 + 0], a0, a1);
                unpack2(accC2[1][jq * 2 + 1], a2, a3);
                c1.x = wk1 * silu_f(a0); c1.y = wk1 * silu_f(a1);
                c1.z = wk1 * silu_f(a2); c1.w = wk1 * silu_f(a3);
                *reinterpret_cast<float4*>(&Csm[0][tid][jq * 4]) = c0;
                *reinterpret_cast<float4*>(&Csm[1][tid][jq * 4]) = c1;
            }
        }
        __syncthreads();
        {   // stage 1: (u, p, ch-of-25), conflict-free
            int u = tid >> 7, p = (tid >> 3) & 15, ch = tid & 7;
            float s = 0.f;
            int kbeg = ch * 25;
            for (int k = kbeg; k < kbeg + 25; k++) s += Csm[u][k][p];
            sPart[u][p][ch] = s;
        }
        __syncthreads();
        if (tid < 32) {  // stage 2
            int u = tid >> 4, p = tid & 15;
            float s = 0.f;
#pragma unroll
            for (int ch = 0; ch < 8; ch++) s += sPart[u][p][ch];
            sA[half * 2 + u][p] = s;
        }
        __syncthreads();
    }

    // ---- O phase: (frame-half, d-pair) split, one uniform LDS.128 per k ----
    int hh = tid >> 7;          // 0: frames 0-3, 1: frames 4-7
    int li = tid & 127;
    int d0 = li * 2;
    u64t a2[2][2];              // [frame-pair within half][dim], lanes = (tt, tt+1)
    a2[0][0] = a2[0][1] = a2[1][0] = a2[1][1] = 0ull;

    const float* F = features + b * KK * DIMN + d0;
    for (int k = 0; k < KK; k += 2) {
        float2 fA = *reinterpret_cast<const float2*>(F + k * DIMN);
        float2 fB = *reinterpret_cast<const float2*>(F + (k + 1) * DIMN);
        ulonglong2 wA = *reinterpret_cast<const ulonglong2*>(&sWt[k][hh * 4]);
        ulonglong2 wB = *reinterpret_cast<const ulonglong2*>(&sWt[k + 1][hh * 4]);
        u64t fAx = pack2(fA.x, fA.x), fAy = pack2(fA.y, fA.y);
        u64t fBx = pack2(fB.x, fB.x), fBy = pack2(fB.y, fB.y);
        a2[0][0] = fma2(fAx, wA.x, a2[0][0]);
        a2[0][1] = fma2(fAy, wA.x, a2[0][1]);
        a2[1][0] = fma2(fAx, wA.y, a2[1][0]);
        a2[1][1] = fma2(fAy, wA.y, a2[1][1]);
        a2[0][0] = fma2(fBx, wB.x, a2[0][0]);
        a2[0][1] = fma2(fBy, wB.x, a2[0][1]);
        a2[1][0] = fma2(fBx, wB.y, a2[1][0]);
        a2[1][1] = fma2(fBy, wB.y, a2[1][1]);
    }

    // ---- epilogue: 4 frames x 2 dims per thread ----
    {
        float2 pbv = *reinterpret_cast<const float2*>(p2b + d0);
        float2 pw[16];
#pragma unroll
        for (int p = 0; p < 16; p++)
            pw[p] = *reinterpret_cast<const float2*>(p2w + p * DIMN + d0);
        int tt0 = hh * 4;
#pragma unroll
        for (int fp = 0; fp < 2; fp++) {
            int tta = tt0 + 2 * fp;
            float oA0, oB0, oA1, oB1;
            unpack2(a2[fp][0], oA0, oB0);   // dim d0: frames tta, tta+1
            unpack2(a2[fp][1], oA1, oB1);   // dim d0+1
            float r00 = oA0 + pbv.x, r01 = oA1 + pbv.y;   // frame tta
            float r10 = oB0 + pbv.x, r11 = oB1 + pbv.y;   // frame tta+1
#pragma unroll
            for (int p = 0; p < 16; p++) {
                float aa = sA[tta][p];
                float ab = sA[tta + 1][p];
                r00 = fmaf(aa, pw[p].x, r00); r01 = fmaf(aa, pw[p].y, r01);
                r10 = fmaf(ab, pw[p].x, r10); r11 = fmaf(ab, pw[p].y, r11);
            }
            int row0 = (b * TFRAMES + t0 + tta) * DIMN + d0;
            *reinterpret_cast<float2*>(out + row0) = make_float2(r00, r01);
            *reinterpret_cast<float2*>(out + row0 + DIMN) = make_float2(r10, r11);
        }
    }
}

// ---------------------------------------------------------------------------
extern "C" void kernel_launch(void* const* d_in, const int* in_sizes, int n_in,
                              void* d_out, int out_size) {
    const float* dur      = (const float*)d_in[1];
    const float* features = (const float*)d_in[2];
    const float* c1w      = (const float*)d_in[3];
    const float* c1b      = (const float*)d_in[4];
    const float* c2w      = (const float*)d_in[5];
    const float* c2b      = (const float*)d_in[6];
    const float* sw1w1    = (const float*)d_in[7];
    const float* sw1b1    = (const float*)d_in[8];
    const float* sw1w2    = (const float*)d_in[9];
    const float* sw1b2    = (const float*)d_in[10];
    const float* sw2w1    = (const float*)d_in[11];
    const float* sw2b1    = (const float*)d_in[12];
    const float* sw2w2    = (const float*)d_in[13];
    const float* sw2b2    = (const float*)d_in[14];
    const float* p1w      = (const float*)d_in[15];
    const float* p1b      = (const float*)d_in[16];
    const float* p2w      = (const float*)d_in[17];
    const float* p2b      = (const float*)d_in[18];
    float* out = (float*)d_out;

    prep_kernel<<<101, 256>>>(dur, features, c1w, c1b, c2w, c2b,
                              sw1w1, sw1b1, sw2w1, sw2b1);

    // PDL: main launches programmatically, overlapping prep's tail with
    // main's launch + prep-independent preamble.
    cudaLaunchConfig_t cfg = {};
    cfg.gridDim = dim3(TFRAMES / TTILE, BB);
    cfg.blockDim = dim3(256);
    cfg.dynamicSmemBytes = 0;
    cudaLaunchAttribute attrs[1];
    attrs[0].id = cudaLaunchAttributeProgrammaticStreamSerialization;
    attrs[0].val.programmaticStreamSerializationAllowed = 1;
    cfg.attrs = attrs;
    cfg.numAttrs = 1;
    cudaLaunchKernelEx(&cfg, main_kernel,
                       features, sw1w1, sw1w2, sw1b2, sw2w1, sw2w2, sw2b2,
                       p1w, p1b, p2w, p2b, out);
}

// round 16
// speedup vs baseline: 1.1634x; 1.0735x over previous
#include <cuda_runtime.h>

#define BB 4
#define KK 200
#define DIMN 256
#define TFRAMES 800
#define TTILE 8
#define NBLK 400

// ---- scratch (no allocations allowed) ----
__device__ float g_start[BB * KK];
__device__ float g_end[BB * KK];
__device__ float g_base1[BB * KK * 16];
__device__ float g_base2[BB * KK * 2];
__device__ unsigned g_barrier;   // monotonic; never reset (replay-safe)

// silu(x) = 0.5*x*(1 + tanh(x/2)) : 1 MUFU + 2 FMA
__device__ __forceinline__ float silu_f(float x) {
    float hx = 0.5f * x;
    float t;
    asm("tanh.approx.f32 %0, %1;" : "=f"(t) : "f"(hx));
    return fmaf(hx, t, hx);
}

// ---- packed f32x2 helpers (sm_100+; FFMA2 is PTX-only) ----
typedef unsigned long long u64t;
__device__ __forceinline__ u64t pack2(float lo, float hi) {
    u64t r;
    asm("mov.b64 %0, {%1, %2};" : "=l"(r) : "f"(lo), "f"(hi));
    return r;
}
__device__ __forceinline__ void unpack2(u64t v, float& lo, float& hi) {
    asm("mov.b64 {%0, %1}, %2;" : "=f"(lo), "=f"(hi) : "l"(v));
}
__device__ __forceinline__ u64t fma2(u64t a, u64t b, u64t c) {
    u64t d;
    asm("fma.rn.f32x2 %0, %1, %2, %3;" : "=l"(d) : "l"(a), "l"(b), "l"(c));
    return d;
}

// ---------------------------------------------------------------------------
// Fused kernel: phase 1 = prep (conv fold on blocks 0-99, cumsum on block
// 100) -> device-wide spin barrier (all 400 blocks co-resident by
// launch_bounds resources) -> phase 2 = main (R12 body, proven 34.5us).
// ---------------------------------------------------------------------------
__global__ __launch_bounds__(256, 3) void fused_kernel(
    const float* __restrict__ dur, const float* __restrict__ features,
    const float* __restrict__ c1w, const float* __restrict__ c1b,
    const float* __restrict__ c2w, const float* __restrict__ c2b,
    const float* __restrict__ sw1w1, const float* __restrict__ sw1b1,
    const float* __restrict__ sw1w2, const float* __restrict__ sw1b2,
    const float* __restrict__ sw2w1, const float* __restrict__ sw2b1,
    const float* __restrict__ sw2w2, const float* __restrict__ sw2b2,
    const float* __restrict__ p1w, const float* __restrict__ p1b,
    const float* __restrict__ p2w, const float* __restrict__ p2b,
    float* __restrict__ out) {
    __shared__ __align__(16) float sE[TTILE][KK];    // raw logits
    __shared__ __align__(16) float sWt[KK][8];       // transposed normalized W
    __shared__ __align__(16) float Csm[2][KK][20];   // W-scaled C, pad 20 (phase1: featS overlay)
    __shared__ __align__(16) float sW2s[256];        // sw1_w2 [16,16]
    __shared__ __align__(16) float sW1p[32];         // interleaved (w1r0, w1r1)
    __shared__ __align__(16) float sB2[16];
    __shared__ float sPart[2][16][8];                // phase1: convS overlay
    __shared__ float sA[TTILE][16];

    int tid = threadIdx.x;
    int b = blockIdx.y;
    int t0 = blockIdx.x * TTILE;
    int lane = tid & 31, wid = tid >> 5;
    int bid = blockIdx.y * 100 + blockIdx.x;   // 0..399

    // =========================== PHASE 1: prep ===========================
    if (bid < 100) {
        // conv fold for pb = bid/25, tokens k0..k0+7
        int pb = bid / 25;
        int k0 = (bid % 25) * 8;
        float* featS = &Csm[0][0][0];            // [10][256] overlay (10KB < 32KB)
        float* convS = &sPart[0][0][0];          // [8][16] overlay

        for (int i = tid; i < 2560; i += 256) {
            int r = i >> 8, d = i & 255;
            int row = k0 - 1 + r;
            featS[r * 256 + d] =
                (row >= 0 && row < KK) ? features[(pb * KK + row) * DIMN + d] : 0.f;
        }
        __syncthreads();

        float acc[16];
#pragma unroll
        for (int c = 0; c < 16; c++) acc[c] = 0.f;
        for (int it = 0; it < 24; it++) {
            int i = it * 32 + lane;
            int j = i >> 8, d = i & 255;
            float f = featS[(wid + j) * 256 + d];
            int off = (j * 256 + d) * 8;
            float4 a0 = *reinterpret_cast<const float4*>(c1w + off);
            float4 a1 = *reinterpret_cast<const float4*>(c1w + off + 4);
            float4 b0 = *reinterpret_cast<const float4*>(c2w + off);
            float4 b1 = *reinterpret_cast<const float4*>(c2w + off + 4);
            acc[0] = fmaf(f, a0.x, acc[0]);  acc[1] = fmaf(f, a0.y, acc[1]);
            acc[2] = fmaf(f, a0.z, acc[2]);  acc[3] = fmaf(f, a0.w, acc[3]);
            acc[4] = fmaf(f, a1.x, acc[4]);  acc[5] = fmaf(f, a1.y, acc[5]);
            acc[6] = fmaf(f, a1.z, acc[6]);  acc[7] = fmaf(f, a1.w, acc[7]);
            acc[8]  = fmaf(f, b0.x, acc[8]);  acc[9]  = fmaf(f, b0.y, acc[9]);
            acc[10] = fmaf(f, b0.z, acc[10]); acc[11] = fmaf(f, b0.w, acc[11]);
            acc[12] = fmaf(f, b1.x, acc[12]); acc[13] = fmaf(f, b1.y, acc[13]);
            acc[14] = fmaf(f, b1.z, acc[14]); acc[15] = fmaf(f, b1.w, acc[15]);
        }
#pragma unroll
        for (int c = 0; c < 16; c++) {
            float v = acc[c];
#pragma unroll
            for (int o = 16; o; o >>= 1) v += __shfl_down_sync(0xffffffffu, v, o);
            if (lane == 0) convS[wid * 16 + c] = v;
        }
        __syncthreads();

        if (tid < 128) {
            int tk = tid >> 4, c = tid & 15;
            float bsl = (c < 8) ? c1b[c] : c2b[c - 8];
            convS[tk * 16 + c] = silu_f(convS[tk * 16 + c] + bsl);
        }
        __syncthreads();

        if (tid < 128) {
            int tk = tid >> 4, i = tid & 15;
            float s = sw1b1[i];
#pragma unroll
            for (int c = 0; c < 8; c++)
                s = fmaf(convS[tk * 16 + c], sw1w1[(2 + c) * 16 + i], s);
            g_base1[(pb * KK + k0 + tk) * 16 + i] = s;
        } else if (tid < 144) {
            int t2 = tid - 128, tk = t2 >> 1, j = t2 & 1;
            float s = sw2b1[j];
#pragma unroll
            for (int c = 0; c < 8; c++)
                s = fmaf(convS[tk * 16 + 8 + c], sw2w1[(2 + c) * 2 + j], s);
            g_base2[(pb * KK + k0 + tk) * 2 + j] = s;
        }
    } else if (bid == 100) {
        // durations cumsum: warp w scans batch w
        if (wid < BB) {
            float carry = 0.f;
            for (int c = 0; c < 7; c++) {
                int idx = c * 32 + lane;
                float d = (idx < KK) ? dur[wid * KK + idx] : 0.f;
                float v = d;
#pragma unroll
                for (int o = 1; o < 32; o <<= 1) {
                    float u = __shfl_up_sync(0xffffffffu, v, o);
                    if (lane >= o) v += u;
                }
                if (idx < KK) {
                    g_end[wid * KK + idx] = carry + v;
                    g_start[wid * KK + idx] = carry + v - d;
                }
                carry += __shfl_sync(0xffffffffu, v, 31);
            }
        }
    }

    // prep-independent preamble for phase 2 (all blocks, overlaps barrier)
    float s2r00 = sw2w1[0], s2r01 = sw2w1[1];
    float s2r10 = sw2w1[2], s2r11 = sw2w1[3];
    float w20 = sw2w2[0], w21 = sw2w2[1], w22 = sw2w2[2], w23 = sw2w2[3];
    float b20 = sw2b2[0], b21 = sw2b2[1];
    float p10 = p1w[0], p11 = p1w[1], pb1 = p1b[0];

    // ---- device-wide barrier (all NBLK blocks co-resident) ----
    __syncthreads();
    if (tid == 0) {
        __threadfence();
        unsigned arrival = atomicAdd(&g_barrier, 1u);
        unsigned target = (arrival / NBLK + 1u) * NBLK;
        while (*((volatile unsigned*)&g_barrier) < target) {}
    }
    __syncthreads();

    // =========================== PHASE 2: main ===========================
    sW2s[tid] = sw1w2[tid];
    if (tid < 16) {
        sW1p[tid * 2]     = sw1w1[tid];
        sW1p[tid * 2 + 1] = sw1w1[16 + tid];
        sB2[tid] = sw1b2[tid];
    }

    float base1[16];
    float base2_0 = 0.f, base2_1 = 0.f, startk = 0.f, endk = 0.f;
    if (tid < KK) {
        startk = g_start[b * KK + tid];
        endk   = g_end[b * KK + tid];
        const float4* bp = reinterpret_cast<const float4*>(g_base1 + (b * KK + tid) * 16);
#pragma unroll
        for (int q = 0; q < 4; q++) {
            float4 v = bp[q];
            base1[q * 4 + 0] = v.x; base1[q * 4 + 1] = v.y;
            base1[q * 4 + 2] = v.z; base1[q * 4 + 3] = v.w;
        }
        base2_0 = g_base2[(b * KK + tid) * 2 + 0];
        base2_1 = g_base2[(b * KK + tid) * 2 + 1];
    }

    // ---- logits for all 8 frames ----
    if (tid < KK) {
#pragma unroll
        for (int tt = 0; tt < TTILE; tt++) {
            float t = (float)(t0 + tt);
            float S = t - startk, E = endk - t;
            float g0  = silu_f(fmaf(S, s2r00, fmaf(E, s2r10, base2_0)));
            float g1  = silu_f(fmaf(S, s2r01, fmaf(E, s2r11, base2_1)));
            float rr0 = silu_f(fmaf(g0, w20, fmaf(g1, w22, b20)));
            float rr1 = silu_f(fmaf(g0, w21, fmaf(g1, w23, b21)));
            sE[tt][tid] = fmaf(rr0, p10, fmaf(rr1, p11, pb1));
        }
    }
    __syncthreads();

    // ---- warp wid: softmax of frame wid -> transposed sWt[k][wid] ----
    {
        float v[7];
        float m = -1e30f;
#pragma unroll
        for (int c = 0; c < 7; c++) {
            int idx = c * 32 + lane;
            v[c] = (idx < KK) ? sE[wid][idx] : -1e30f;
            m = fmaxf(m, v[c]);
        }
#pragma unroll
        for (int o = 16; o; o >>= 1) m = fmaxf(m, __shfl_xor_sync(0xffffffffu, m, o));
        float s = 0.f;
#pragma unroll
        for (int c = 0; c < 7; c++) {
            v[c] = __expf(v[c] - m);
            if (c * 32 + lane < KK) s += v[c];
        }
#pragma unroll
        for (int o = 16; o; o >>= 1) s += __shfl_xor_sync(0xffffffffu, s, o);
        float invs = 1.0f / s;
#pragma unroll
        for (int c = 0; c < 7; c++) {
            int idx = c * 32 + lane;
            if (idx < KK) sWt[idx][wid] = v[c] * invs;
        }
    }
    __syncthreads();

    // ---- C phase + A reduction, 2 register-blocked frames, FFMA2 on j ----
    const float2* w1v = reinterpret_cast<const float2*>(sW1p);
    for (int half = 0; half < 4; half++) {
        if (tid < KK) {
            float tA = (float)(t0 + half * 2);
            float S0 = tA - startk, E0 = endk - tA;
            float S1 = S0 + 1.0f,   E1 = E0 - 1.0f;
            u64t accC2[2][8];
            {
                const u64t* b2v = reinterpret_cast<const u64t*>(sB2);
#pragma unroll
                for (int j2 = 0; j2 < 8; j2++) {
                    u64t bv = b2v[j2];
                    accC2[0][j2] = bv;
                    accC2[1][j2] = bv;
                }
            }
#pragma unroll
            for (int i = 0; i < 16; i++) {
                float2 wp = w1v[i];
                float h0 = silu_f(fmaf(S0, wp.x, fmaf(E0, wp.y, base1[i])));
                float h1 = silu_f(fmaf(S1, wp.x, fmaf(E1, wp.y, base1[i])));
                u64t h02 = pack2(h0, h0);
                u64t h12 = pack2(h1, h1);
                const ulonglong2* wrow = reinterpret_cast<const ulonglong2*>(sW2s + i * 16);
#pragma unroll
                for (int jq = 0; jq < 4; jq++) {
                    ulonglong2 wv = wrow[jq];
                    accC2[0][jq * 2 + 0] = fma2(h02, wv.x, accC2[0][jq * 2 + 0]);
                    accC2[0][jq * 2 + 1] = fma2(h02, wv.y, accC2[0][jq * 2 + 1]);
                    accC2[1][jq * 2 + 0] = fma2(h12, wv.x, accC2[1][jq * 2 + 0]);
                    accC2[1][jq * 2 + 1] = fma2(h12, wv.y, accC2[1][jq * 2 + 1]);
                }
            }
            float wk0 = sWt[tid][half * 2 + 0];
            float wk1 = sWt[tid][half * 2 + 1];
#pragma unroll
            for (int jq = 0; jq < 4; jq++) {
                float a0, a1, a2, a3;
                float4 c0, c1;
                unpack2(accC2[0][jq * 2 + 0], a0, a1);
                unpack2(accC2[0][jq * 2 + 1], a2, a3);
                c0.x = wk0 * silu_f(a0); c0.y = wk0 * silu_f(a1);
                c0.z = wk0 * silu_f(a2); c0.w = wk0 * silu_f(a3);
                unpack2(accC2[1][jq * 2 + 0], a0, a1);
                unpack2(accC2[1][jq * 2 + 1], a2, a3);
                c1.x = wk1 * silu_f(a0); c1.y = wk1 * silu_f(a1);
                c1.z = wk1 * silu_f(a2); c1.w = wk1 * silu_f(a3);
                *reinterpret_cast<float4*>(&Csm[0][tid][jq * 4]) = c0;
                *reinterpret_cast<float4*>(&Csm[1][tid][jq * 4]) = c1;
            }
        }
        __syncthreads();
        {   // stage 1: (u, p, ch-of-25), conflict-free
            int u = tid >> 7, p = (tid >> 3) & 15, ch = tid & 7;
            float s = 0.f;
            int kbeg = ch * 25;
            for (int k = kbeg; k < kbeg + 25; k++) s += Csm[u][k][p];
            sPart[u][p][ch] = s;
        }
        __syncthreads();
        if (tid < 32) {  // stage 2
            int u = tid >> 4, p = tid & 15;
            float s = 0.f;
#pragma unroll
            for (int ch = 0; ch < 8; ch++) s += sPart[u][p][ch];
            sA[half * 2 + u][p] = s;
        }
        __syncthreads();
    }

    // ---- O phase: (frame-half, d-pair) split, one uniform LDS.128 per k ----
    int hh = tid >> 7;          // 0: frames 0-3, 1: frames 4-7
    int li = tid & 127;
    int d0 = li * 2;
    u64t a2[2][2];              // [frame-pair within half][dim], lanes = (tt, tt+1)
    a2[0][0] = a2[0][1] = a2[1][0] = a2[1][1] = 0ull;

    const float* F = features + b * KK * DIMN + d0;
    for (int k = 0; k < KK; k += 2) {
        float2 fA = *reinterpret_cast<const float2*>(F + k * DIMN);
        float2 fB = *reinterpret_cast<const float2*>(F + (k + 1) * DIMN);
        ulonglong2 wA = *reinterpret_cast<const ulonglong2*>(&sWt[k][hh * 4]);
        ulonglong2 wB = *reinterpret_cast<const ulonglong2*>(&sWt[k + 1][hh * 4]);
        u64t fAx = pack2(fA.x, fA.x), fAy = pack2(fA.y, fA.y);
        u64t fBx = pack2(fB.x, fB.x), fBy = pack2(fB.y, fB.y);
        a2[0][0] = fma2(fAx, wA.x, a2[0][0]);
        a2[0][1] = fma2(fAy, wA.x, a2[0][1]);
        a2[1][0] = fma2(fAx, wA.y, a2[1][0]);
        a2[1][1] = fma2(fAy, wA.y, a2[1][1]);
        a2[0][0] = fma2(fBx, wB.x, a2[0][0]);
        a2[0][1] = fma2(fBy, wB.x, a2[0][1]);
        a2[1][0] = fma2(fBx, wB.y, a2[1][0]);
        a2[1][1] = fma2(fBy, wB.y, a2[1][1]);
    }

    // ---- epilogue: 4 frames x 2 dims per thread ----
    {
        float2 pbv = *reinterpret_cast<const float2*>(p2b + d0);
        float2 pw[16];
#pragma unroll
        for (int p = 0; p < 16; p++)
            pw[p] = *reinterpret_cast<const float2*>(p2w + p * DIMN + d0);
        int tt0 = hh * 4;
#pragma unroll
        for (int fp = 0; fp < 2; fp++) {
            int tta = tt0 + 2 * fp;
            float oA0, oB0, oA1, oB1;
            unpack2(a2[fp][0], oA0, oB0);   // dim d0: frames tta, tta+1
            unpack2(a2[fp][1], oA1, oB1);   // dim d0+1
            float r00 = oA0 + pbv.x, r01 = oA1 + pbv.y;   // frame tta
            float r10 = oB0 + pbv.x, r11 = oB1 + pbv.y;   // frame tta+1
#pragma unroll
            for (int p = 0; p < 16; p++) {
                float aa = sA[tta][p];
                float ab = sA[tta + 1][p];
                r00 = fmaf(aa, pw[p].x, r00); r01 = fmaf(aa, pw[p].y, r01);
                r10 = fmaf(ab, pw[p].x, r10); r11 = fmaf(ab, pw[p].y, r11);
            }
            int row0 = (b * TFRAMES + t0 + tta) * DIMN + d0;
            *reinterpret_cast<float2*>(out + row0) = make_float2(r00, r01);
            *reinterpret_cast<float2*>(out + row0 + DIMN) = make_float2(r10, r11);
        }
    }
}

// ---------------------------------------------------------------------------
extern "C" void kernel_launch(void* const* d_in, const int* in_sizes, int n_in,
                              void* d_out, int out_size) {
    const float* dur      = (const float*)d_in[1];
    const float* features = (const float*)d_in[2];
    const float* c1w      = (const float*)d_in[3];
    const float* c1b      = (const float*)d_in[4];
    const float* c2w      = (const float*)d_in[5];
    const float* c2b      = (const float*)d_in[6];
    const float* sw1w1    = (const float*)d_in[7];
    const float* sw1b1    = (const float*)d_in[8];
    const float* sw1w2    = (const float*)d_in[9];
    const float* sw1b2    = (const float*)d_in[10];
    const float* sw2w1    = (const float*)d_in[11];
    const float* sw2b1    = (const float*)d_in[12];
    const float* sw2w2    = (const float*)d_in[13];
    const float* sw2b2    = (const float*)d_in[14];
    const float* p1w      = (const float*)d_in[15];
    const float* p1b      = (const float*)d_in[16];
    const float* p2w      = (const float*)d_in[17];
    const float* p2b      = (const float*)d_in[18];
    float* out = (float*)d_out;

    fused_kernel<<<dim3(TFRAMES / TTILE, BB), 256>>>(
        dur, features, c1w, c1b, c2w, c2b,
        sw1w1, sw1b1, sw1w2, sw1b2, sw2w1, sw2b1, sw2w2, sw2b2,
        p1w, p1b, p2w, p2b, out);
}